// round 4
// baseline (speedup 1.0000x reference)
#include <cuda_runtime.h>

#define NB 512
#define TT 1024
#define CC 64

typedef unsigned long long u64;

__device__ __forceinline__ u64 pk(float lo, float hi) {
    u64 r; asm("mov.b64 %0, {%1,%2};" : "=l"(r) : "f"(lo), "f"(hi)); return r;
}
__device__ __forceinline__ void upk(u64 v, float& lo, float& hi) {
    asm("mov.b64 {%0,%1}, %2;" : "=f"(lo), "=f"(hi) : "l"(v));
}
__device__ __forceinline__ u64 ffma2(u64 a, u64 b, u64 c) {
    u64 d; asm("fma.rn.f32x2 %0, %1, %2, %3;" : "=l"(d) : "l"(a), "l"(b), "l"(c)); return d;
}
__device__ __forceinline__ u64 fmul2(u64 a, u64 b) {
    u64 d; asm("mul.rn.f32x2 %0, %1, %2;" : "=l"(d) : "l"(a), "l"(b)); return d;
}
__device__ __forceinline__ u64 fadd2(u64 a, u64 b) {
    u64 d; asm("add.rn.f32x2 %0, %1, %2;" : "=l"(d) : "l"(a), "l"(b)); return d;
}
__device__ __forceinline__ float frcp(float x) {
    float r; asm("rcp.approx.f32 %0, %1;" : "=f"(r) : "f"(x)); return r;
}

__global__ void __launch_bounds__(128, 4) crf_fwd_kernel(
    const float* __restrict__ logits,   // [NB, TT, CC]
    const float* __restrict__ trans,    // [CC, CC]  trans[i][j] = score j->i
    const float* __restrict__ init,     // [CC]
    const int*   __restrict__ lengths,  // [NB]
    const int*   __restrict__ tags,     // [NB, TT]
    float*       __restrict__ out)      // [NB]
{
    __shared__ __align__(16) u64    part[4][32];   // per-warp partial dots (packed pairs)
    __shared__ __align__(16) float2 wpair[CC];     // duplicated pairs {w[j], w[j]}
    __shared__ float rn_sh[2];                     // normalizer, parity double-buffered
    __shared__ float cacc_sh;
    __shared__ float gpart[4];

    const int tid  = threadIdx.x;
    const int wid  = tid >> 5;
    const int lane = tid & 31;
    const int b    = blockIdx.x;                   // one batch per CTA

    const float* lg = logits + (size_t)b * TT * CC;
    const int len = lengths[b];                    // in [2, 1024], uniform per CTA
    const int j0 = wid * 16;                       // this warp's j-chunk

    // ---- EP[k] = { exp(trans[lane][j0+k]), exp(trans[lane+32][j0+k]) }, k=0..15
    u64 EP[16];
    {
        const float4* r0 = (const float4*)(trans + lane * CC + j0);
        const float4* r1 = (const float4*)(trans + (lane + 32) * CC + j0);
        #pragma unroll
        for (int q = 0; q < 4; ++q) {
            float4 x0 = __ldg(r0 + q);
            float4 x1 = __ldg(r1 + q);
            EP[4*q+0] = pk(__expf(x0.x), __expf(x1.x));
            EP[4*q+1] = pk(__expf(x0.y), __expf(x1.y));
            EP[4*q+2] = pk(__expf(x0.z), __expf(x1.z));
            EP[4*q+3] = pk(__expf(x0.w), __expf(x1.w));
        }
    }

    // ---- pipeline registers (warp-specialized) ----
    u64   Fcur = 0;                 // warp0: exp(logit_t) packed, for current t
    float LpA = 0.0f, LpB = 0.0f;   // warp0: raw logits for t+1 (prefetched)
    float f0cur = 0.0f, l0nxt = 0.0f; // warp1: scalar state-0 versions
    float w_lo = 0.0f, w_hi = 0.0f; // warp0: current w
    float cacc = 0.0f, lnApp = 0.0f; // warp1: shift accounting

    if (wid == 0) {
        // w_0 = exp(init + logits[0]); store duplicated
        const float e0 = __expf(__ldg(init + lane)      + __ldg(lg + lane));
        const float e1 = __expf(__ldg(init + lane + 32) + __ldg(lg + lane + 32));
        wpair[lane]      = make_float2(e0, e0);
        wpair[lane + 32] = make_float2(e1, e1);
        // F for t=1; raw logits for t=2
        Fcur = pk(__expf(__ldg(lg + CC + lane)), __expf(__ldg(lg + CC + 32 + lane)));
        const int t2 = (2 < len) ? 2 : (len - 1);
        LpA = __ldg(lg + t2 * CC + lane);
        LpB = __ldg(lg + t2 * CC + 32 + lane);
    } else if (wid == 1) {
        f0cur = __expf(__ldg(lg + CC));                // exp(logits[1][0])
        const int t2 = (2 < len) ? 2 : (len - 1);
        l0nxt = __ldg(lg + t2 * CC);
    }
    if (tid == 0) { rn_sh[0] = 1.0f; rn_sh[1] = 1.0f; }
    __syncthreads();

    #pragma unroll 1
    for (int t = 1; t < len; ++t) {
        // ---- phase A: per-warp side work + 16-term partial dot ----
        u64 Fnext = 0; float nLpA = 0.0f, nLpB = 0.0f, nf0 = 0.0f, nl0 = 0.0f;
        if (wid == 0) {
            Fnext = pk(__expf(LpA), __expf(LpB));      // F for t+1
            const int tp = (t + 2 < len) ? (t + 2) : (len - 1);
            nLpA = __ldg(lg + tp * CC + lane);
            nLpB = __ldg(lg + tp * CC + 32 + lane);
        } else if (wid == 1) {
            nf0 = __expf(l0nxt);
            const int tp = (t + 2 < len) ? (t + 2) : (len - 1);
            nl0 = __ldg(lg + tp * CC);
        } else if (wid == 3) {
            const int tp = (t + 4 < len) ? (t + 4) : (len - 1);
            const float* p = lg + (size_t)tp * CC;
            asm volatile("prefetch.global.L1 [%0];" :: "l"(p));
            asm volatile("prefetch.global.L1 [%0];" :: "l"(p + 32));
        }

        const ulonglong2* wv = (const ulonglong2*)wpair;  // pairs {2i, 2i+1}
        u64 a0 = 0ull, a1 = 0ull, a2 = 0ull, a3 = 0ull;
        #pragma unroll
        for (int q = 0; q < 4; ++q) {
            ulonglong2 b0 = wv[8 * wid + 2 * q];
            ulonglong2 b1 = wv[8 * wid + 2 * q + 1];
            a0 = ffma2(EP[4*q + 0], b0.x, a0);
            a1 = ffma2(EP[4*q + 1], b0.y, a1);
            a2 = ffma2(EP[4*q + 2], b1.x, a2);
            a3 = ffma2(EP[4*q + 3], b1.y, a3);
        }
        part[wid][lane] = fadd2(fadd2(a0, a1), fadd2(a2, a3));
        __syncthreads();                               // bar1: partials visible

        // ---- phase B: specialized ----
        if (wid == 0) {
            const u64 D = fadd2(fadd2(part[0][lane], part[1][lane]),
                                fadd2(part[2][lane], part[3][lane]));
            const float rp = rn_sh[(t - 1) & 1];
            const u64 w = fmul2(fmul2(D, Fcur), pk(rp, rp));
            upk(w, w_lo, w_hi);
            wpair[lane]      = make_float2(w_lo, w_lo);
            wpair[lane + 32] = make_float2(w_hi, w_hi);
            Fcur = Fnext; LpA = nLpA; LpB = nLpB;
        } else if (wid == 1) {
            // scalar shadow of w[0] -> next normalizer (off warp0's path)
            const float* pf = (const float*)part;       // low floats of packed pairs
            const float D0 = (pf[0] + pf[64]) + (pf[128] + pf[192]);
            const float rp = rn_sh[(t - 1) & 1];
            float v = (D0 * f0cur) * rp;
            cacc += lnApp;                              // account R applied this step
            v = fminf(fmaxf(v, 1e-30f), 1e30f);
            const float rn = frcp(v);
            lnApp = -__logf(rn);
            rn_sh[t & 1] = rn;                          // consumed by warp0 at t+1
            f0cur = nf0; l0nxt = nl0;
        }
        __syncthreads();                               // bar2: w visible
    }

    if (wid == 1 && lane == 0) cacc_sh = cacc;

    // ---- gold path score: block-parallel over t ----
    const int* tg = tags + (size_t)b * TT;
    float gs = 0.0f;
    for (int t = 1 + tid; t < len; t += 128) {
        const int tc = __ldg(tg + t);
        const int tp = __ldg(tg + t - 1);
        gs += __ldg(trans + tc * CC + tp) + __ldg(lg + t * CC + tc);
    }
    #pragma unroll
    for (int o = 16; o; o >>= 1) gs += __shfl_xor_sync(0xffffffffu, gs, o);
    if (lane == 0) gpart[wid] = gs;
    __syncthreads();

    if (wid == 0) {
        float s = w_lo + w_hi;                          // final w (last iteration)
        #pragma unroll
        for (int o = 16; o; o >>= 1) s += __shfl_xor_sync(0xffffffffu, s, o);
        if (lane == 0) {
            const int tg0 = __ldg(tg);
            const float first = __ldg(init + tg0) + __ldg(lg + tg0);
            const float logZ = cacc_sh + __logf(s);
            const float gold = first + gpart[0] + gpart[1] + gpart[2] + gpart[3];
            out[b] = logZ - gold;
        }
    }
}

extern "C" void kernel_launch(void* const* d_in, const int* in_sizes, int n_in,
                              void* d_out, int out_size)
{
    const float* logits = (const float*)d_in[0];
    const float* trans  = (const float*)d_in[1];
    const float* init   = (const float*)d_in[2];
    const int*   lens   = (const int*)  d_in[3];
    const int*   tags   = (const int*)  d_in[4];
    float*       out    = (float*)d_out;

    crf_fwd_kernel<<<NB, 128>>>(logits, trans, init, lens, tags, out);
}

// round 6
// speedup vs baseline: 1.2970x; 1.2970x over previous
#include <cuda_runtime.h>

#define NB 512
#define TT 1024
#define CC 64

typedef unsigned long long u64;

__device__ __forceinline__ u64 pk(float lo, float hi) {
    u64 r; asm("mov.b64 %0, {%1,%2};" : "=l"(r) : "f"(lo), "f"(hi)); return r;
}
__device__ __forceinline__ void upk(u64 v, float& lo, float& hi) {
    asm("mov.b64 {%0,%1}, %2;" : "=f"(lo), "=f"(hi) : "l"(v));
}
__device__ __forceinline__ u64 ffma2(u64 a, u64 b, u64 c) {
    u64 d; asm("fma.rn.f32x2 %0, %1, %2, %3;" : "=l"(d) : "l"(a), "l"(b), "l"(c)); return d;
}
__device__ __forceinline__ u64 fmul2(u64 a, u64 b) {
    u64 d; asm("mul.rn.f32x2 %0, %1, %2;" : "=l"(d) : "l"(a), "l"(b)); return d;
}
__device__ __forceinline__ u64 fadd2(u64 a, u64 b) {
    u64 d; asm("add.rn.f32x2 %0, %1, %2;" : "=l"(d) : "l"(a), "l"(b)); return d;
}
__device__ __forceinline__ float frcp(float x) {
    float r; asm("rcp.approx.f32 %0, %1;" : "=f"(r) : "f"(x)); return r;
}

__global__ void __launch_bounds__(128, 1) crf_fwd_kernel(
    const float* __restrict__ logits,   // [NB, TT, CC]
    const float* __restrict__ trans,    // [CC, CC]  trans[i][j] = score j->i
    const float* __restrict__ init,     // [CC]
    const int*   __restrict__ lengths,  // [NB]
    const int*   __restrict__ tags,     // [NB, TT]
    float*       __restrict__ out)      // [NB]
{
    __shared__ __align__(16) float wbuf[4][2][2 * CC];  // duplicated pairs, double-buffered

    const int wid  = threadIdx.x >> 5;
    const int lane = threadIdx.x & 31;
    const int g    = blockIdx.x * 4 + wid;          // grid=128 -> g in [0,512)

    const float* lg = logits + (size_t)g * TT * CC;
    const int len = lengths[g];                     // in [2, 1024]

    // ---- build packed E rows: EP[j] = { exp(trans[lane][j]), exp(trans[lane+32][j]) }
    u64 EP[CC];
    {
        const float4* r0 = (const float4*)(trans + lane * CC);
        const float4* r1 = (const float4*)(trans + (lane + 32) * CC);
        #pragma unroll
        for (int q = 0; q < 16; ++q) {
            float4 x0 = __ldg(r0 + q);
            float4 x1 = __ldg(r1 + q);
            EP[4*q+0] = pk(__expf(x0.x), __expf(x1.x));
            EP[4*q+1] = pk(__expf(x0.y), __expf(x1.y));
            EP[4*q+2] = pk(__expf(x0.z), __expf(x1.z));
            EP[4*q+3] = pk(__expf(x0.w), __expf(x1.w));
        }
    }

    // ---- w_0 = exp(init + logits[0]) (C_0 = 0), stored duplicated
    float w_lo, w_hi;
    {
        float a0 = __ldg(init + lane)      + __ldg(lg + lane);
        float a1 = __ldg(init + lane + 32) + __ldg(lg + lane + 32);
        w_lo = __expf(a0);
        w_hi = __expf(a1);
        float2* ws = (float2*)(&wbuf[wid][0][0]);
        ws[lane]      = make_float2(w_lo, w_lo);
        ws[lane + 32] = make_float2(w_hi, w_hi);
        __syncwarp();
    }

    // ---- logit pipeline: F = exp(logits[t]) current; L1 = raw logits[t+1]; L2 = raw logits[t+2]
    u64 F;
    float L1A, L1B, L2A, L2B;
    {
        F = pk(__expf(__ldg(lg + CC + lane)), __expf(__ldg(lg + CC + 32 + lane)));
        const int c2 = (2 < len) ? 2 : (len - 1);
        const int c3 = (3 < len) ? 3 : (len - 1);
        L1A = __ldg(lg + c2 * CC + lane);
        L1B = __ldg(lg + c2 * CC + 32 + lane);
        L2A = __ldg(lg + c3 * CC + lane);
        L2B = __ldg(lg + c3 * CC + 32 + lane);
    }

    u64 Rp = pk(1.0f, 1.0f);   // shift factor applied this step
    float lnApp = 0.0f;        // -ln(Rp), added to C when Rp is applied
    float cacc  = 0.0f;        // running shift C
    int buf = 0;

    for (int t = 1; t < len; ++t) {
        // ---- issue LDG for logits[t+3] FIRST: ~2 full steps of latency cover
        const int tn = (t + 3 < len) ? (t + 3) : (len - 1);
        const float LnA = __ldg(lg + tn * CC + lane);
        const float LnB = __ldg(lg + tn * CC + 32 + lane);

        // F for t+1 (MUFU early, consumed at iteration end)
        const float FnA = __expf(L1A);
        const float FnB = __expf(L1B);

        // ---- dot: D[i] = sum_j E[i][j] * w[j], packed over the two owned states
        const ulonglong2* wv = (const ulonglong2*)(&wbuf[wid][buf][0]);
        u64 a0 = 0ull, a1 = 0ull, a2 = 0ull, a3 = 0ull;
        #pragma unroll
        for (int q = 0; q < 32; q += 2) {
            ulonglong2 b0 = wv[q];       // {w_{2q} dup, w_{2q+1} dup}
            ulonglong2 b1 = wv[q + 1];
            a0 = ffma2(EP[2*q + 0], b0.x, a0);
            a1 = ffma2(EP[2*q + 1], b0.y, a1);
            a2 = ffma2(EP[2*q + 2], b1.x, a2);
            a3 = ffma2(EP[2*q + 3], b1.y, a3);
        }
        const u64 d = fadd2(fadd2(a0, a1), fadd2(a2, a3));

        // ---- w_t = D * exp(logit_t) * R   (linear-domain update, no exp/log on chain)
        const u64 w = fmul2(fmul2(d, F), Rp);
        upk(w, w_lo, w_hi);
        float2* ws = (float2*)(&wbuf[wid][buf ^ 1][0]);
        ws[lane]      = make_float2(w_lo, w_lo);
        ws[lane + 32] = make_float2(w_hi, w_hi);
        __syncwarp();
        buf ^= 1;

        // ---- off-critical-path bookkeeping
        cacc += lnApp;                          // account for the R applied this step
        // normalize the NEXT step by the actual stored w_t[0] (stable lag-1 scheme)
        float vb = __shfl_sync(0xffffffffu, w_lo, 0);
        vb = fminf(fmaxf(vb, 1e-30f), 1e30f);   // keep finite/nonzero
        const float rn = frcp(vb);              // R for next step (hidden by next dot)
        lnApp = -__logf(rn);                    // exact ln of the factor actually applied
        Rp = pk(rn, rn);

        // rotate logit pipeline
        F = pk(FnA, FnB);
        L1A = L2A; L1B = L2B;
        L2A = LnA; L2B = LnB;
    }

    // ---- logZ = C + ln( sum_j w_{L-1}[j] )
    float s = w_lo + w_hi;
    #pragma unroll
    for (int o = 16; o; o >>= 1) s += __shfl_xor_sync(0xffffffffu, s, o);
    const float logZ = cacc + __logf(s);

    // ---- gold path score (lane-parallel over t; order-free sum, fp32-safe)
    const int* tg = tags + (size_t)g * TT;
    const int tg0 = __ldg(tg);
    const float first = __ldg(init + tg0) + __ldg(lg + tg0);
    float gs = 0.0f;
    for (int t = 1 + lane; t < len; t += 32) {
        const int tc = __ldg(tg + t);
        const int tp = __ldg(tg + t - 1);
        gs += __ldg(trans + tc * CC + tp) + __ldg(lg + t * CC + tc);
    }
    #pragma unroll
    for (int o = 16; o; o >>= 1) gs += __shfl_xor_sync(0xffffffffu, gs, o);

    if (lane == 0) out[g] = logZ - (first + gs);
}

extern "C" void kernel_launch(void* const* d_in, const int* in_sizes, int n_in,
                              void* d_out, int out_size)
{
    const float* logits = (const float*)d_in[0];
    const float* trans  = (const float*)d_in[1];
    const float* init   = (const float*)d_in[2];
    const int*   lens   = (const int*)  d_in[3];
    const int*   tags   = (const int*)  d_in[4];
    float*       out    = (float*)d_out;

    crf_fwd_kernel<<<NB / 4, 128>>>(logits, trans, init, lens, tags, out);
}

// round 9
// speedup vs baseline: 1.8894x; 1.4567x over previous
#include <cuda_runtime.h>

#define NB 512
#define TT 1024
#define CC 64

typedef unsigned int u32;
typedef unsigned short u16;

__device__ __forceinline__ u32 pkbf2(float lo, float hi) {
    // d[31:16] = bf16(hi), d[15:0] = bf16(lo)
    u32 r; asm("cvt.rn.bf16x2.f32 %0, %1, %2;" : "=r"(r) : "f"(hi), "f"(lo)); return r;
}
__device__ __forceinline__ u16 f2bf(float x) {
    u16 r; asm("cvt.rn.bf16.f32 %0, %1;" : "=h"(r) : "f"(x)); return r;
}
__device__ __forceinline__ float frcp(float x) {
    float r; asm("rcp.approx.f32 %0, %1;" : "=f"(r) : "f"(x)); return r;
}
__device__ __forceinline__ void mma16816(float& c0, float& c1, float& c2, float& c3,
                                         u32 a0, u32 a1, u32 a2, u32 a3,
                                         u32 b0, u32 b1) {
    asm("mma.sync.aligned.m16n8k16.row.col.f32.bf16.bf16.f32 "
        "{%0,%1,%2,%3}, {%4,%5,%6,%7}, {%8,%9}, {%0,%1,%2,%3};"
        : "+f"(c0), "+f"(c1), "+f"(c2), "+f"(c3)
        : "r"(a0), "r"(a1), "r"(a2), "r"(a3), "r"(b0), "r"(b1));
}

__global__ void __launch_bounds__(128, 1) crf_fwd_kernel(
    const float* __restrict__ logits,   // [NB, TT, CC]
    const float* __restrict__ trans,    // [CC, CC]  trans[i][j] = score j->i
    const float* __restrict__ init,     // [CC]
    const int*   __restrict__ lengths,  // [NB]
    const int*   __restrict__ tags,     // [NB, TT]
    float*       __restrict__ out)      // [NB]
{
    // per-warp w vector in bf16, double-buffered (64 bf16 = 128 B per buffer)
    __shared__ __align__(16) u16 wsh[4][2][CC];

    const int wid  = threadIdx.x >> 5;
    const int lane = threadIdx.x & 31;
    const int g    = blockIdx.x * 4 + wid;          // grid=128 -> g in [0,512)

    const float* lg = logits + (size_t)g * TT * CC;
    const int len = lengths[g];                     // in [2, 1024], uniform per warp

    const int gid = lane >> 2;                      // 0..7
    const int tig = lane & 3;                       // 0..3
    const int r1  = gid + 16 * tig;                 // this lane's owned states
    const int r2  = r1 + 8;                         // (lane 0 -> rows 0, 8)

    // ---- preload E = exp(trans) as bf16 A-fragments: EA[mt][kt][4]
    // A tile (mt,kt) = E[16mt .. +15][16kt .. +15], row-major, m16k16 fragment layout.
    u32 EA[4][4][4];
    #pragma unroll
    for (int mt = 0; mt < 4; ++mt) {
        const int row = 16 * mt + gid;
        #pragma unroll
        for (int kt = 0; kt < 4; ++kt) {
            const int col = 16 * kt + 2 * tig;
            const float e00 = __expf(__ldg(trans + row * CC + col));
            const float e01 = __expf(__ldg(trans + row * CC + col + 1));
            const float e10 = __expf(__ldg(trans + (row + 8) * CC + col));
            const float e11 = __expf(__ldg(trans + (row + 8) * CC + col + 1));
            const float e08 = __expf(__ldg(trans + row * CC + col + 8));
            const float e09 = __expf(__ldg(trans + row * CC + col + 9));
            const float e18 = __expf(__ldg(trans + (row + 8) * CC + col + 8));
            const float e19 = __expf(__ldg(trans + (row + 8) * CC + col + 9));
            EA[mt][kt][0] = pkbf2(e00, e01);   // rows gid,   cols 2tig..+1
            EA[mt][kt][1] = pkbf2(e10, e11);   // rows gid+8, cols 2tig..+1
            EA[mt][kt][2] = pkbf2(e08, e09);   // rows gid,   cols 2tig+8..+9
            EA[mt][kt][3] = pkbf2(e18, e19);   // rows gid+8, cols 2tig+8..+9
        }
    }

    // ---- w_0 = exp(init + logits[0])
    float w1 = __expf(__ldg(init + r1) + __ldg(lg + r1));
    float w2 = __expf(__ldg(init + r2) + __ldg(lg + r2));
    wsh[wid][0][r1] = f2bf(w1);
    wsh[wid][0][r2] = f2bf(w2);
    __syncwarp();

    // ---- logit pipeline: F for t=1; raw logits for t+1, t+2 (distance-3 LDG cover)
    float F1 = __expf(__ldg(lg + CC + r1));
    float F2 = __expf(__ldg(lg + CC + r2));
    const int c2i = (2 < len) ? 2 : (len - 1);
    const int c3i = (3 < len) ? 3 : (len - 1);
    float L1A = __ldg(lg + c2i * CC + r1), L1B = __ldg(lg + c2i * CC + r2);
    float L2A = __ldg(lg + c3i * CC + r1), L2B = __ldg(lg + c3i * CC + r2);

    float rn = 1.0f;      // normalizer applied this step (lag-1)
    float lnApp = 0.0f;   // -ln(rn)
    float cacc = 0.0f;    // running log-shift
    int buf = 0;

    for (int t = 1; t < len; ++t) {
        // LDG for logits[t+3] first — ~2 steps of latency cover
        const int tn = (t + 3 < len) ? (t + 3) : (len - 1);
        const float LnA = __ldg(lg + tn * CC + r1);
        const float LnB = __ldg(lg + tn * CC + r2);
        // F for t+1 (MUFU off the critical chain)
        const float FnA = __expf(L1A);
        const float FnB = __expf(L1B);

        // ---- B fragments: B[k][n] = w[k] for all n (broadcast LDS.b32 pairs)
        const u32* wp = (const u32*)(&wsh[wid][buf][0]);
        u32 b0[4], b1[4];
        #pragma unroll
        for (int kt = 0; kt < 4; ++kt) {
            b0[kt] = wp[8 * kt + tig];        // k = 16kt+2tig, +1
            b1[kt] = wp[8 * kt + tig + 4];    // k = 16kt+2tig+8, +9
        }

        // ---- D = E * w via 16 HMMA (4 independent chains of depth 4)
        float c[4][4];
        #pragma unroll
        for (int mt = 0; mt < 4; ++mt)
            #pragma unroll
            for (int i = 0; i < 4; ++i) c[mt][i] = 0.0f;
        #pragma unroll
        for (int kt = 0; kt < 4; ++kt)
            #pragma unroll
            for (int mt = 0; mt < 4; ++mt)
                mma16816(c[mt][0], c[mt][1], c[mt][2], c[mt][3],
                         EA[mt][kt][0], EA[mt][kt][1], EA[mt][kt][2], EA[mt][kt][3],
                         b0[kt], b1[kt]);

        // every lane holds D[16mt+gid] (c0) and D[16mt+gid+8] (c2) for all mt;
        // select the tile this lane owns (mt = tig) — 4-way select, no dynamic index
        float D1 = c[0][0], D2 = c[0][2];
        if (tig == 1) { D1 = c[1][0]; D2 = c[1][2]; }
        if (tig == 2) { D1 = c[2][0]; D2 = c[2][2]; }
        if (tig == 3) { D1 = c[3][0]; D2 = c[3][2]; }

        // ---- w_t = D * exp(logit_t) * rn   (fp32)
        w1 = D1 * F1 * rn;
        w2 = D2 * F2 * rn;
        wsh[wid][buf ^ 1][r1] = f2bf(w1);
        wsh[wid][buf ^ 1][r2] = f2bf(w2);
        __syncwarp();
        buf ^= 1;

        // ---- off-chain bookkeeping (stable lag-1 normalizer on actual w_t[0])
        cacc += lnApp;                              // account rn applied this step
        float vb = __shfl_sync(0xffffffffu, w1, 0); // w_t[0] lives on lane 0
        vb = fminf(fmaxf(vb, 1e-30f), 1e30f);
        rn = frcp(vb);
        lnApp = -__logf(rn);

        F1 = FnA; F2 = FnB;
        L1A = L2A; L1B = L2B;
        L2A = LnA; L2B = LnB;
    }

    // ---- logZ = C + ln( sum_j w_{L-1}[j] )   (f32 w values, all 64 states once)
    float s = w1 + w2;
    #pragma unroll
    for (int o = 16; o; o >>= 1) s += __shfl_xor_sync(0xffffffffu, s, o);
    const float logZ = cacc + __logf(s);

    // ---- gold path score (lane-parallel over t; order-free sum)
    const int* tg = tags + (size_t)g * TT;
    const int tg0 = __ldg(tg);
    const float first = __ldg(init + tg0) + __ldg(lg + tg0);
    float gs = 0.0f;
    for (int t = 1 + lane; t < len; t += 32) {
        const int tc = __ldg(tg + t);
        const int tp = __ldg(tg + t - 1);
        gs += __ldg(trans + tc * CC + tp) + __ldg(lg + t * CC + tc);
    }
    #pragma unroll
    for (int o = 16; o; o >>= 1) gs += __shfl_xor_sync(0xffffffffu, gs, o);

    if (lane == 0) out[g] = logZ - (first + gs);
}

extern "C" void kernel_launch(void* const* d_in, const int* in_sizes, int n_in,
                              void* d_out, int out_size)
{
    const float* logits = (const float*)d_in[0];
    const float* trans  = (const float*)d_in[1];
    const float* init   = (const float*)d_in[2];
    const int*   lens   = (const int*)  d_in[3];
    const int*   tags   = (const int*)  d_in[4];
    float*       out    = (float*)d_out;

    crf_fwd_kernel<<<NB / 4, 128>>>(logits, trans, init, lens, tags, out);
}